// round 9
// baseline (speedup 1.0000x reference)
#include <cuda_runtime.h>
#include <cuda_bf16.h>
#include <cuda_fp8.h>
#include <cstdint>
#include <math.h>

typedef __nv_bfloat16 bf16;

#define Bz 32
#define Dz 2048
#define Gz 8192
#define Vz 10000
#define Tz 20
#define Xz 36

#define WSCALE 32.f
#define HSCALE 8.f
#define UNSCALE (1.f / 256.f)

#define PBLOCKS 256

// ---------------- device scratch (allocation-free rule: __device__ globals) ----------------
__device__ __align__(256) uint8_t g_f8Ah [Gz*Dz];   // e4m3: Wih_a[:,0:2048]*32
__device__ __align__(256) uint8_t g_f8Ahh[Gz*Dz];   // e4m3: Whh_a*32
__device__ __align__(256) uint8_t g_f8Lh [Gz*Dz];   // e4m3: Wih_l[:,0:2048]*32
__device__ __align__(256) uint8_t g_f8Lhh[Gz*Dz];   // e4m3: Whh_l*32
__device__ __align__(256) bf16 g_bAv [Gz*Dz];       // Wih_a[:,2048:4096] (v_bar block)
__device__ __align__(256) bf16 g_bAe [Gz*Dz];       // Wih_a[:,4096:6144] (emb block)
__device__ __align__(256) bf16 g_bLv [Gz*Dz];       // Wih_l[:,2048:4096] (v_hat block)
__device__ __align__(256) bf16 g_bFC [Vz*Dz];       // Wfc
__device__ __align__(256) bf16 g_embsB[Bz*Tz*Dz];   // [t*32+b, k]
__device__ __align__(256) bf16 g_vbarB[Bz*Dz];
__device__ __align__(256) bf16 g_vhatB[Bz*Dz];
__device__ __align__(256) uint8_t g_h8a[Bz*Dz];     // e4m3: h_a*8
__device__ __align__(256) uint8_t g_h8l[Bz*Dz];     // e4m3: h_l*8
__device__ __align__(256) bf16 g_hlAll[Tz*Bz*Dz];   // rows t*32+b (bf16 for logits GEMM)
__device__ __align__(256) float g_caF[Bz*Dz];
__device__ __align__(256) float g_clF[Bz*Dz];
__device__ __align__(256) float g_zF[5*Bz*Gz];      // 5 partial-z slabs
__device__ __align__(256) float g_prevAF[Bz*Gz];
__device__ __align__(256) float g_preLF[Bz*Gz];
__device__ __align__(256) float g_preAF[Bz*Tz*Gz];
__device__ unsigned g_bar;                           // persistent-kernel barrier counter

__device__ __forceinline__ uint32_t smem_u32(const void* p) {
    return (uint32_t)__cvta_generic_to_shared(p);
}

// ---------------- fp32 -> bf16 strided column-block conversion (4 elems/thread) ----------
__global__ void k_conv(const float* __restrict__ src, int stride, int off,
                       bf16* __restrict__ dst, int total4) {
    int i = blockIdx.x * 256 + threadIdx.x;
    if (i >= total4) return;
    int base = i << 2;
    int n = base >> 11, k = base & 2047;
    const float* p = src + (size_t)n * stride + off + k;
    bf16* q = dst + base;
    q[0] = __float2bfloat16(p[0]);
    q[1] = __float2bfloat16(p[1]);
    q[2] = __float2bfloat16(p[2]);
    q[3] = __float2bfloat16(p[3]);
}

// ---------------- fp32 -> e4m3 (x WSCALE) conversion, packed 4B store ----------------
__global__ void k_conv8(const float* __restrict__ src, int stride, int off,
                        uint8_t* __restrict__ dst, int total4) {
    int i = blockIdx.x * 256 + threadIdx.x;
    if (i >= total4) return;
    int base = i << 2;
    int n = base >> 11, k = base & 2047;
    const float* p = src + (size_t)n * stride + off + k;
    uint32_t b0 = __nv_cvt_float_to_fp8(p[0] * WSCALE, __NV_SATFINITE, __NV_E4M3);
    uint32_t b1 = __nv_cvt_float_to_fp8(p[1] * WSCALE, __NV_SATFINITE, __NV_E4M3);
    uint32_t b2 = __nv_cvt_float_to_fp8(p[2] * WSCALE, __NV_SATFINITE, __NV_E4M3);
    uint32_t b3 = __nv_cvt_float_to_fp8(p[3] * WSCALE, __NV_SATFINITE, __NV_E4M3);
    *(uint32_t*)(dst + base) = b0 | (b1 << 8) | (b2 << 16) | (b3 << 24);
}

// ---------------- features reduction ----------------
__global__ void k_feat(const float* __restrict__ f) {
    int i = blockIdx.x * 256 + threadIdx.x;
    if (i >= Bz * Dz) return;
    int b = i >> 11, k = i & 2047;
    const float* p = f + (size_t)b * Xz * Dz + k;
    float s = 0.f;
#pragma unroll
    for (int x = 0; x < Xz; x++) s += p[x * Dz];
    g_vbarB[i] = __float2bfloat16(s * (1.f / 36.f));
    g_vhatB[i] = __float2bfloat16(s);
}

// ---------------- embedding gather, t-major rows ----------------
__global__ void k_embs(const float* __restrict__ emb, const int* __restrict__ cap) {
    int i = blockIdx.x * 256 + threadIdx.x;
    if (i >= Bz * Tz * Dz) return;
    int k = i & 2047, r = i >> 11;
    int t = r >> 5, b = r & 31;
    int tok = cap[b * Tz + t];
    g_embsB[i] = __float2bfloat16(emb[(size_t)tok * Dz + k]);
}

#define STAGES 4

// ---------------- generic bf16 tensor-core GEMM (precompute + logits) ----------------
__global__ void __launch_bounds__(128)
k_gemm(const bf16* __restrict__ A1, const bf16* __restrict__ W1, int K1,
       const bf16* __restrict__ A2, const bf16* __restrict__ W2, int K2,
       const float* __restrict__ P, int ldP, int pLocal,
       const float* __restrict__ bias1, const float* __restrict__ bias2,
       float* __restrict__ Z, int ldZ, int N, int remapBT)
{
    __shared__ __align__(128) bf16 sA[STAGES][32 * 72];
    __shared__ __align__(128) bf16 sW[STAGES][32 * 72];

    const int tid   = threadIdx.x;
    const int lane  = tid & 31;
    const int warp  = tid >> 5;
    const int nBlk  = blockIdx.x * 32;
    const int mBase = blockIdx.y * 32;
    const int s1      = K1 >> 6;
    const int nStages = (K1 + K2) >> 6;

    const int lr0 = tid >> 3;
    const int lc  = (tid & 7) * 8;

    auto loadStage = [&](int s, int buf) {
        int kg = s << 6;
        const bf16* Ap; const bf16* Wp; int K; int ko;
        if (s < s1) { Ap = A1; Wp = W1; K = K1; ko = kg; }
        else        { Ap = A2; Wp = W2; K = K2; ko = kg - (s1 << 6); }
#pragma unroll
        for (int half = 0; half < 2; half++) {
            int row = lr0 + half * 16;
            uint32_t da = smem_u32(&sA[buf][row * 72 + lc]);
            const bf16* ga = Ap + (size_t)(mBase + row) * K + ko + lc;
            asm volatile("cp.async.cg.shared.global [%0], [%1], 16;\n" :: "r"(da), "l"(ga));
            int wr = nBlk + row;
            uint32_t dw = smem_u32(&sW[buf][row * 72 + lc]);
            const bf16* gw = Wp + (size_t)(wr < N ? wr : 0) * K + ko + lc;
            int sz = (wr < N) ? 16 : 0;
            asm volatile("cp.async.cg.shared.global [%0], [%1], 16, %2;\n"
                         :: "r"(dw), "l"(gw), "r"(sz));
        }
    };

#pragma unroll
    for (int s = 0; s < STAGES - 1; s++) {
        if (s < nStages) loadStage(s, s);
        asm volatile("cp.async.commit_group;\n");
    }

    float d0[4] = {0, 0, 0, 0}, d1[4] = {0, 0, 0, 0};
    const int aR = lane & 15;
    const int aC = (lane >> 4) * 8;
    const int bR = warp * 8 + (lane & 7);
    const int bC = ((lane >> 3) & 1) * 8;

    for (int s = 0; s < nStages; s++) {
        if (s + STAGES - 1 < nStages) loadStage(s + STAGES - 1, (s + STAGES - 1) % STAGES);
        asm volatile("cp.async.commit_group;\n");
        asm volatile("cp.async.wait_group %0;\n" :: "n"(STAGES - 1));
        __syncthreads();
        const bf16* pa = sA[s % STAGES];
        const bf16* pw = sW[s % STAGES];
#pragma unroll
        for (int kk = 0; kk < 64; kk += 16) {
            uint32_t a0[4], a1[4], bb[2];
            uint32_t ad0 = smem_u32(&pa[aR * 72 + kk + aC]);
            uint32_t ad1 = smem_u32(&pa[(aR + 16) * 72 + kk + aC]);
            uint32_t adb = smem_u32(&pw[bR * 72 + kk + bC]);
            asm volatile("ldmatrix.sync.aligned.m8n8.x4.shared.b16 {%0,%1,%2,%3}, [%4];\n"
                : "=r"(a0[0]), "=r"(a0[1]), "=r"(a0[2]), "=r"(a0[3]) : "r"(ad0));
            asm volatile("ldmatrix.sync.aligned.m8n8.x4.shared.b16 {%0,%1,%2,%3}, [%4];\n"
                : "=r"(a1[0]), "=r"(a1[1]), "=r"(a1[2]), "=r"(a1[3]) : "r"(ad1));
            asm volatile("ldmatrix.sync.aligned.m8n8.x2.shared.b16 {%0,%1}, [%2];\n"
                : "=r"(bb[0]), "=r"(bb[1]) : "r"(adb));
            asm volatile("mma.sync.aligned.m16n8k16.row.col.f32.bf16.bf16.f32 "
                "{%0,%1,%2,%3}, {%4,%5,%6,%7}, {%8,%9}, {%0,%1,%2,%3};\n"
                : "+f"(d0[0]), "+f"(d0[1]), "+f"(d0[2]), "+f"(d0[3])
                : "r"(a0[0]), "r"(a0[1]), "r"(a0[2]), "r"(a0[3]), "r"(bb[0]), "r"(bb[1]));
            asm volatile("mma.sync.aligned.m16n8k16.row.col.f32.bf16.bf16.f32 "
                "{%0,%1,%2,%3}, {%4,%5,%6,%7}, {%8,%9}, {%0,%1,%2,%3};\n"
                : "+f"(d1[0]), "+f"(d1[1]), "+f"(d1[2]), "+f"(d1[3])
                : "r"(a1[0]), "r"(a1[1]), "r"(a1[2]), "r"(a1[3]), "r"(bb[0]), "r"(bb[1]));
        }
        __syncthreads();
    }

    const int g = lane >> 2, tg = lane & 3;
    const int ncol = nBlk + warp * 8 + tg * 2;
#pragma unroll
    for (int mt = 0; mt < 2; mt++) {
        const float* dd = mt ? d1 : d0;
#pragma unroll
        for (int rr = 0; rr < 2; rr++) {
            int m = mt * 16 + rr * 8 + g;
            int row = mBase + m;
            int prow = pLocal ? (row & 31) : row;
            int orow = remapBT ? ((row & 31) * Tz + (row >> 5)) : row;
#pragma unroll
            for (int cc = 0; cc < 2; cc++) {
                int col = ncol + cc;
                if (col < N) {
                    float v = dd[rr * 2 + cc];
                    if (P)     v += P[(size_t)prow * ldP + col];
                    if (bias1) v += bias1[col];
                    if (bias2) v += bias2[col];
                    Z[(size_t)orow * ldZ + col] = v;
                }
            }
        }
    }
}

// ---------------- fp8 GEMM tile (device fn): one 32x32 N-tile, KTILE=128 e4m3 ----------
__device__ __forceinline__ void gemm_tile8(
    const uint8_t* __restrict__ A, const uint8_t* __restrict__ W,
    float* __restrict__ Z, int kOff, int kLen, int nBlk,
    uint8_t (&sA)[STAGES][32 * 144], uint8_t (&sW)[STAGES][32 * 144])
{
    const int tid  = threadIdx.x;
    const int lane = tid & 31;
    const int warp = tid >> 5;
    const int nStages = kLen >> 7;

    const int lr0 = tid >> 3;
    const int lc  = (tid & 7) * 16;

    auto loadStage = [&](int s, int buf) {
        int ko = (s << 7) + kOff;
#pragma unroll
        for (int half = 0; half < 2; half++) {
            int row = lr0 + half * 16;
            uint32_t da = smem_u32(&sA[buf][row * 144 + lc]);
            const uint8_t* ga = A + (size_t)row * Dz + ko + lc;
            asm volatile("cp.async.cg.shared.global [%0], [%1], 16;\n" :: "r"(da), "l"(ga));
            uint32_t dw = smem_u32(&sW[buf][row * 144 + lc]);
            const uint8_t* gw = W + (size_t)(nBlk + row) * Dz + ko + lc;
            asm volatile("cp.async.cg.shared.global [%0], [%1], 16;\n" :: "r"(dw), "l"(gw));
        }
    };

#pragma unroll
    for (int s = 0; s < STAGES - 1; s++) {
        if (s < nStages) loadStage(s, s);
        asm volatile("cp.async.commit_group;\n");
    }

    float d0[4] = {0, 0, 0, 0}, d1[4] = {0, 0, 0, 0};
    const int aR  = lane & 15;
    const int aCB = (lane >> 4) * 16;
    const int bR  = warp * 8 + (lane & 7);
    const int bCB = ((lane >> 3) & 1) * 16;

    for (int s = 0; s < nStages; s++) {
        if (s + STAGES - 1 < nStages) loadStage(s + STAGES - 1, (s + STAGES - 1) % STAGES);
        asm volatile("cp.async.commit_group;\n");
        asm volatile("cp.async.wait_group %0;\n" :: "n"(STAGES - 1));
        __syncthreads();
        const uint8_t* pa = sA[s % STAGES];
        const uint8_t* pw = sW[s % STAGES];
#pragma unroll
        for (int kk = 0; kk < 128; kk += 32) {
            uint32_t a0[4], a1[4], bb[2];
            uint32_t ad0 = smem_u32(&pa[aR * 144 + kk + aCB]);
            uint32_t ad1 = smem_u32(&pa[(aR + 16) * 144 + kk + aCB]);
            uint32_t adb = smem_u32(&pw[bR * 144 + kk + bCB]);
            asm volatile("ldmatrix.sync.aligned.m8n8.x4.shared.b16 {%0,%1,%2,%3}, [%4];\n"
                : "=r"(a0[0]), "=r"(a0[1]), "=r"(a0[2]), "=r"(a0[3]) : "r"(ad0));
            asm volatile("ldmatrix.sync.aligned.m8n8.x4.shared.b16 {%0,%1,%2,%3}, [%4];\n"
                : "=r"(a1[0]), "=r"(a1[1]), "=r"(a1[2]), "=r"(a1[3]) : "r"(ad1));
            asm volatile("ldmatrix.sync.aligned.m8n8.x2.shared.b16 {%0,%1}, [%2];\n"
                : "=r"(bb[0]), "=r"(bb[1]) : "r"(adb));
            asm volatile("mma.sync.aligned.m16n8k32.row.col.f32.e4m3.e4m3.f32 "
                "{%0,%1,%2,%3}, {%4,%5,%6,%7}, {%8,%9}, {%0,%1,%2,%3};\n"
                : "+f"(d0[0]), "+f"(d0[1]), "+f"(d0[2]), "+f"(d0[3])
                : "r"(a0[0]), "r"(a0[1]), "r"(a0[2]), "r"(a0[3]), "r"(bb[0]), "r"(bb[1]));
            asm volatile("mma.sync.aligned.m16n8k32.row.col.f32.e4m3.e4m3.f32 "
                "{%0,%1,%2,%3}, {%4,%5,%6,%7}, {%8,%9}, {%0,%1,%2,%3};\n"
                : "+f"(d1[0]), "+f"(d1[1]), "+f"(d1[2]), "+f"(d1[3])
                : "r"(a1[0]), "r"(a1[1]), "r"(a1[2]), "r"(a1[3]), "r"(bb[0]), "r"(bb[1]));
        }
        __syncthreads();
    }

    const int g = lane >> 2, tg = lane & 3;
    const int ncol = nBlk + warp * 8 + tg * 2;
#pragma unroll
    for (int mt = 0; mt < 2; mt++) {
        const float* dd = mt ? d1 : d0;
#pragma unroll
        for (int rr = 0; rr < 2; rr++) {
            int m = mt * 16 + rr * 8 + g;
#pragma unroll
            for (int cc = 0; cc < 2; cc++) {
                int col = ncol + cc;
                Z[(size_t)m * Gz + col] = dd[rr * 2 + cc] * UNSCALE;
            }
        }
    }
}

// ---------------- grid barrier (cumulative counter; all PBLOCKS blocks resident) --------
__device__ __forceinline__ void gbar(unsigned target) {
    __threadfence();
    __syncthreads();
    if (threadIdx.x == 0) {
        atomicAdd(&g_bar, 1u);
        while (*(volatile unsigned*)&g_bar < target) __nanosleep(64);
        __threadfence();
    }
    __syncthreads();
}

// ---------------- LSTM cell as device fn (reads z via L2 to avoid stale L1) -------------
__device__ __forceinline__ void cell_phase(
    const float* __restrict__ z0, const float* __restrict__ z1,
    const float* __restrict__ z2, const float* __restrict__ pre,
    float* __restrict__ c, uint8_t* __restrict__ h8, bf16* __restrict__ hCopy)
{
    for (int i = blockIdx.x * 128 + threadIdx.x; i < Bz * Dz; i += PBLOCKS * 128) {
        int b = i >> 11, d = i & 2047;
        size_t o = (size_t)b * Gz + d;
        float ii = __ldcg(z0 + o)          + __ldcg(z1 + o)          + pre[o];
        float ff = __ldcg(z0 + o + Dz)     + __ldcg(z1 + o + Dz)     + pre[o + Dz];
        float gg = __ldcg(z0 + o + 2 * Dz) + __ldcg(z1 + o + 2 * Dz) + pre[o + 2 * Dz];
        float oo = __ldcg(z0 + o + 3 * Dz) + __ldcg(z1 + o + 3 * Dz) + pre[o + 3 * Dz];
        if (z2) {
            ii += __ldcg(z2 + o);
            ff += __ldcg(z2 + o + Dz);
            gg += __ldcg(z2 + o + 2 * Dz);
            oo += __ldcg(z2 + o + 3 * Dz);
        }
        float si = 1.f / (1.f + expf(-ii));
        float sf = 1.f / (1.f + expf(-ff));
        float so = 1.f / (1.f + expf(-oo));
        float tg = tanhf(gg);
        float cn = sf * c[i] + si * tg;
        c[i] = cn;
        float hv = so * tanhf(cn);
        h8[i] = __nv_cvt_float_to_fp8(hv * HSCALE, __NV_SATFINITE, __NV_E4M3);
        if (hCopy) hCopy[i] = __float2bfloat16(hv);
    }
}

// ---------------- persistent loop kernel: all 20 steps, 4 phases/step --------------------
__global__ void __launch_bounds__(128)
k_loop(const float* __restrict__ preA, const float* __restrict__ preL,
       float* __restrict__ ca, float* __restrict__ cl,
       uint8_t* __restrict__ h8a, uint8_t* __restrict__ h8l,
       bf16* __restrict__ hlAll, float* __restrict__ zz)
{
    __shared__ __align__(128) uint8_t sA[STAGES][32 * 144];
    __shared__ __align__(128) uint8_t sW[STAGES][32 * 144];

    const size_t SLAB = (size_t)Bz * Gz;
    unsigned phase = 0;

    for (int t = 0; t < Tz; t++) {
        // Phase X: 768 jobs = {hl@Ah, ha@Ahh, hl@Lhh} x 256 N-tiles
        for (int j = blockIdx.x; j < 768; j += PBLOCKS) {
            int m = j >> 8, n = j & 255;
            const uint8_t* A = (m == 1) ? h8a : h8l;
            const uint8_t* W = (m == 0) ? g_f8Ah : (m == 1) ? g_f8Ahh : g_f8Lhh;
            gemm_tile8(A, W, zz + (size_t)m * SLAB, 0, Dz, n * 32, sA, sW);
        }
        phase++; gbar(phase * PBLOCKS);

        // cellA: z_a = slab0 + slab1 + preA[t]
        cell_phase(zz, zz + SLAB, nullptr, preA + (size_t)t * SLAB, ca, h8a, nullptr);
        phase++; gbar(phase * PBLOCKS);

        // Phase Y: 512 jobs = ha(new)@Lh, K-split halves x 256 N-tiles
        for (int j = blockIdx.x; j < 512; j += PBLOCKS) {
            int half = j >> 8, n = j & 255;
            gemm_tile8(h8a, g_f8Lh, zz + (size_t)(3 + half) * SLAB,
                       half * 1024, 1024, n * 32, sA, sW);
        }
        phase++; gbar(phase * PBLOCKS);

        // cellL: z_l = slab2 + slab3 + slab4 + preL
        cell_phase(zz + 2 * SLAB, zz + 3 * SLAB, zz + 4 * SLAB, preL,
                   cl, h8l, hlAll + (size_t)t * Bz * Dz);
        phase++; gbar(phase * PBLOCKS);
    }
}

// ---------------- in-place log_softmax over V per (b,t) row ----------------
__global__ void k_lsm(float* __restrict__ out) {
    __shared__ float red[8];
    int r = blockIdx.x;
    float* p = out + (size_t)r * Vz;
    int tid = threadIdx.x;
    float m = -1e30f;
    for (int i = tid; i < Vz; i += 256) m = fmaxf(m, p[i]);
#pragma unroll
    for (int o = 16; o > 0; o >>= 1) m = fmaxf(m, __shfl_xor_sync(0xffffffffu, m, o));
    if ((tid & 31) == 0) red[tid >> 5] = m;
    __syncthreads();
    if (tid == 0) {
        float mm = red[0];
        for (int j = 1; j < 8; j++) mm = fmaxf(mm, red[j]);
        red[0] = mm;
    }
    __syncthreads();
    m = red[0];
    __syncthreads();
    float s = 0.f;
    for (int i = tid; i < Vz; i += 256) s += expf(p[i] - m);
#pragma unroll
    for (int o = 16; o > 0; o >>= 1) s += __shfl_xor_sync(0xffffffffu, s, o);
    if ((tid & 31) == 0) red[tid >> 5] = s;
    __syncthreads();
    if (tid == 0) {
        float ss = 0.f;
        for (int j = 0; j < 8; j++) ss += red[j];
        red[0] = ss;
    }
    __syncthreads();
    float lse = m + logf(red[0]);
    for (int i = tid; i < Vz; i += 256) p[i] -= lse;
}

// ---------------- host ----------------
extern "C" void kernel_launch(void* const* d_in, const int* in_sizes, int n_in,
                              void* d_out, int out_size) {
    const float* features = (const float*)d_in[0];
    const int*   caption  = (const int*)  d_in[1];
    const float* emb      = (const float*)d_in[2];
    const float* Wih_a    = (const float*)d_in[3];
    const float* Whh_a    = (const float*)d_in[4];
    const float* bih_a    = (const float*)d_in[5];
    const float* bhh_a    = (const float*)d_in[6];
    const float* Wih_l    = (const float*)d_in[7];
    const float* Whh_l    = (const float*)d_in[8];
    const float* bih_l    = (const float*)d_in[9];
    const float* bhh_l    = (const float*)d_in[10];
    const float* Wfc      = (const float*)d_in[17];
    const float* bfc      = (const float*)d_in[18];
    float* out = (float*)d_out;

    uint8_t *f8Ah, *f8Ahh, *f8Lh, *f8Lhh, *h8a, *h8l;
    bf16 *bAv, *bAe, *bLv, *bFC, *embsB, *vbarB, *vhatB, *hlAll;
    float *ca, *cl, *zz, *prevA, *preL, *preA;
    unsigned* barp;
    cudaGetSymbolAddress((void**)&f8Ah,  g_f8Ah);
    cudaGetSymbolAddress((void**)&f8Ahh, g_f8Ahh);
    cudaGetSymbolAddress((void**)&f8Lh,  g_f8Lh);
    cudaGetSymbolAddress((void**)&f8Lhh, g_f8Lhh);
    cudaGetSymbolAddress((void**)&h8a,   g_h8a);
    cudaGetSymbolAddress((void**)&h8l,   g_h8l);
    cudaGetSymbolAddress((void**)&bAv,   g_bAv);
    cudaGetSymbolAddress((void**)&bAe,   g_bAe);
    cudaGetSymbolAddress((void**)&bLv,   g_bLv);
    cudaGetSymbolAddress((void**)&bFC,   g_bFC);
    cudaGetSymbolAddress((void**)&embsB, g_embsB);
    cudaGetSymbolAddress((void**)&vbarB, g_vbarB);
    cudaGetSymbolAddress((void**)&vhatB, g_vhatB);
    cudaGetSymbolAddress((void**)&hlAll, g_hlAll);
    cudaGetSymbolAddress((void**)&ca,    g_caF);
    cudaGetSymbolAddress((void**)&cl,    g_clF);
    cudaGetSymbolAddress((void**)&zz,    g_zF);
    cudaGetSymbolAddress((void**)&prevA, g_prevAF);
    cudaGetSymbolAddress((void**)&preL,  g_preLF);
    cudaGetSymbolAddress((void**)&preA,  g_preAF);
    cudaGetSymbolAddress((void**)&barp,  g_bar);

    // init recurrent state + barrier counter (graph replays need fresh counter)
    cudaMemsetAsync(ca,  0, (size_t)Bz * Dz * sizeof(float));
    cudaMemsetAsync(cl,  0, (size_t)Bz * Dz * sizeof(float));
    cudaMemsetAsync(h8a, 0, (size_t)Bz * Dz);
    cudaMemsetAsync(h8l, 0, (size_t)Bz * Dz);
    cudaMemsetAsync(barp, 0, sizeof(unsigned));

    // one-shot precompute
    k_feat<<<(Bz * Dz + 255) / 256, 256>>>(features);
    k_embs<<<(Bz * Tz * Dz + 255) / 256, 256>>>(emb, caption);

    const int cv4 = Gz * Dz / 4;
    k_conv8<<<cv4 / 256, 256>>>(Wih_a, 3 * Dz, 0,  f8Ah,  cv4);
    k_conv8<<<cv4 / 256, 256>>>(Whh_a, Dz,     0,  f8Ahh, cv4);
    k_conv8<<<cv4 / 256, 256>>>(Wih_l, 2 * Dz, 0,  f8Lh,  cv4);
    k_conv8<<<cv4 / 256, 256>>>(Whh_l, Dz,     0,  f8Lhh, cv4);
    k_conv<<<cv4 / 256, 256>>>(Wih_a, 3 * Dz, Dz,     bAv, cv4);
    k_conv<<<cv4 / 256, 256>>>(Wih_a, 3 * Dz, 2 * Dz, bAe, cv4);
    k_conv<<<cv4 / 256, 256>>>(Wih_l, 2 * Dz, Dz,     bLv, cv4);
    k_conv<<<(Vz * Dz / 4 + 255) / 256, 256>>>(Wfc, Dz, 0, bFC, Vz * Dz / 4);

    dim3 blk(128);
    // prevA[b,:] = v_bar @ bAv^T + bih_a + bhh_a
    k_gemm<<<dim3(Gz / 32, 1), blk>>>(vbarB, bAv, Dz, vbarB, bAv, 0,
                                      nullptr, 0, 0, bih_a, bhh_a, prevA, Gz, Gz, 0);
    // preA[t*32+b,:] = prevA[b,:] + e_{b,t} @ bAe^T
    k_gemm<<<dim3(Gz / 32, Tz), blk>>>(embsB, bAe, Dz, embsB, bAe, 0,
                                       prevA, Gz, 1, nullptr, nullptr, preA, Gz, Gz, 0);
    // preL[b,:] = v_hat @ bLv^T + bih_l + bhh_l
    k_gemm<<<dim3(Gz / 32, 1), blk>>>(vhatB, bLv, Dz, vhatB, bLv, 0,
                                      nullptr, 0, 0, bih_l, bhh_l, preL, Gz, Gz, 0);

    // persistent loop: all 20 steps in one launch, grid barriers between phases
    k_loop<<<PBLOCKS, blk>>>(preA, preL, ca, cl, h8a, h8l, hlAll, zz);

    // batched logits: rows r=t*32+b of hlAll @ Wfc^T + bfc -> out[b][t][:]
    k_gemm<<<dim3((Vz + 31) / 32, Tz), blk>>>(hlAll, bFC, Dz, hlAll, bFC, 0,
                                              nullptr, 0, 0, bfc, nullptr,
                                              out, Vz, Vz, 1);
    k_lsm<<<Bz * Tz, 256>>>(out);
}

// round 10
// speedup vs baseline: 1.0226x; 1.0226x over previous
#include <cuda_runtime.h>
#include <cuda_bf16.h>
#include <cuda_fp8.h>
#include <cstdint>
#include <math.h>

typedef __nv_bfloat16 bf16;

#define Bz 32
#define Dz 2048
#define Gz 8192
#define Vz 10000
#define Tz 20
#define Xz 36

#define WSCALE 32.f
#define HSCALE 8.f
#define UNSCALE (1.f / 256.f)

// ---------------- device scratch (allocation-free rule: __device__ globals) ----------------
__device__ __align__(256) uint8_t g_f8Ah [Gz*Dz];   // e4m3: Wih_a[:,0:2048]*32
__device__ __align__(256) uint8_t g_f8Ahh[Gz*Dz];   // e4m3: Whh_a*32
__device__ __align__(256) uint8_t g_f8Lh [Gz*Dz];   // e4m3: Wih_l[:,0:2048]*32
__device__ __align__(256) uint8_t g_f8Lhh[Gz*Dz];   // e4m3: Whh_l*32
__device__ __align__(256) bf16 g_bAv [Gz*Dz];       // Wih_a[:,2048:4096] (v_bar block)
__device__ __align__(256) bf16 g_bAe [Gz*Dz];       // Wih_a[:,4096:6144] (emb block)
__device__ __align__(256) bf16 g_bLv [Gz*Dz];       // Wih_l[:,2048:4096] (v_hat block)
__device__ __align__(256) bf16 g_bFC [Vz*Dz];       // Wfc
__device__ __align__(256) bf16 g_embsB[Bz*Tz*Dz];   // [t*32+b, k]
__device__ __align__(256) bf16 g_vbarB[Bz*Dz];
__device__ __align__(256) bf16 g_vhatB[Bz*Dz];
__device__ __align__(256) uint8_t g_h8a[Bz*Dz];     // e4m3: h_a*8
__device__ __align__(256) uint8_t g_h8l[Bz*Dz];     // e4m3: h_l*8
__device__ __align__(256) bf16 g_hlAll[Tz*Bz*Dz];   // rows t*32+b (bf16 for logits GEMM)
__device__ __align__(256) float g_caF[Bz*Dz];
__device__ __align__(256) float g_clF[Bz*Dz];
__device__ __align__(256) float g_zF[5*Bz*Gz];      // 5 partial-z slabs
__device__ __align__(256) float g_prevAF[Bz*Gz];
__device__ __align__(256) float g_preLF[Bz*Gz];
__device__ __align__(256) float g_preAF[Bz*Tz*Gz];
__device__ unsigned g_bar;                           // persistent-kernel barrier counter

__device__ __forceinline__ uint32_t smem_u32(const void* p) {
    return (uint32_t)__cvta_generic_to_shared(p);
}

// ---------------- fp32 -> bf16 strided column-block conversion (4 elems/thread) ----------
__global__ void k_conv(const float* __restrict__ src, int stride, int off,
                       bf16* __restrict__ dst, int total4) {
    int i = blockIdx.x * 256 + threadIdx.x;
    if (i >= total4) return;
    int base = i << 2;
    int n = base >> 11, k = base & 2047;
    const float* p = src + (size_t)n * stride + off + k;
    bf16* q = dst + base;
    q[0] = __float2bfloat16(p[0]);
    q[1] = __float2bfloat16(p[1]);
    q[2] = __float2bfloat16(p[2]);
    q[3] = __float2bfloat16(p[3]);
}

// ---------------- fp32 -> e4m3 (x WSCALE) conversion, packed 4B store ----------------
__global__ void k_conv8(const float* __restrict__ src, int stride, int off,
                        uint8_t* __restrict__ dst, int total4) {
    int i = blockIdx.x * 256 + threadIdx.x;
    if (i >= total4) return;
    int base = i << 2;
    int n = base >> 11, k = base & 2047;
    const float* p = src + (size_t)n * stride + off + k;
    uint32_t b0 = __nv_cvt_float_to_fp8(p[0] * WSCALE, __NV_SATFINITE, __NV_E4M3);
    uint32_t b1 = __nv_cvt_float_to_fp8(p[1] * WSCALE, __NV_SATFINITE, __NV_E4M3);
    uint32_t b2 = __nv_cvt_float_to_fp8(p[2] * WSCALE, __NV_SATFINITE, __NV_E4M3);
    uint32_t b3 = __nv_cvt_float_to_fp8(p[3] * WSCALE, __NV_SATFINITE, __NV_E4M3);
    *(uint32_t*)(dst + base) = b0 | (b1 << 8) | (b2 << 16) | (b3 << 24);
}

// ---------------- features reduction ----------------
__global__ void k_feat(const float* __restrict__ f) {
    int i = blockIdx.x * 256 + threadIdx.x;
    if (i >= Bz * Dz) return;
    int b = i >> 11, k = i & 2047;
    const float* p = f + (size_t)b * Xz * Dz + k;
    float s = 0.f;
#pragma unroll
    for (int x = 0; x < Xz; x++) s += p[x * Dz];
    g_vbarB[i] = __float2bfloat16(s * (1.f / 36.f));
    g_vhatB[i] = __float2bfloat16(s);
}

// ---------------- embedding gather, t-major rows ----------------
__global__ void k_embs(const float* __restrict__ emb, const int* __restrict__ cap) {
    int i = blockIdx.x * 256 + threadIdx.x;
    if (i >= Bz * Tz * Dz) return;
    int k = i & 2047, r = i >> 11;
    int t = r >> 5, b = r & 31;
    int tok = cap[b * Tz + t];
    g_embsB[i] = __float2bfloat16(emb[(size_t)tok * Dz + k]);
}

#define STAGES 4

// ---------------- generic bf16 tensor-core GEMM (precompute + logits) ----------------
__global__ void __launch_bounds__(128)
k_gemm(const bf16* __restrict__ A1, const bf16* __restrict__ W1, int K1,
       const bf16* __restrict__ A2, const bf16* __restrict__ W2, int K2,
       const float* __restrict__ P, int ldP, int pLocal,
       const float* __restrict__ bias1, const float* __restrict__ bias2,
       float* __restrict__ Z, int ldZ, int N, int remapBT)
{
    __shared__ __align__(128) bf16 sA[STAGES][32 * 72];
    __shared__ __align__(128) bf16 sW[STAGES][32 * 72];

    const int tid   = threadIdx.x;
    const int lane  = tid & 31;
    const int warp  = tid >> 5;
    const int nBlk  = blockIdx.x * 32;
    const int mBase = blockIdx.y * 32;
    const int s1      = K1 >> 6;
    const int nStages = (K1 + K2) >> 6;

    const int lr0 = tid >> 3;
    const int lc  = (tid & 7) * 8;

    auto loadStage = [&](int s, int buf) {
        int kg = s << 6;
        const bf16* Ap; const bf16* Wp; int K; int ko;
        if (s < s1) { Ap = A1; Wp = W1; K = K1; ko = kg; }
        else        { Ap = A2; Wp = W2; K = K2; ko = kg - (s1 << 6); }
#pragma unroll
        for (int half = 0; half < 2; half++) {
            int row = lr0 + half * 16;
            uint32_t da = smem_u32(&sA[buf][row * 72 + lc]);
            const bf16* ga = Ap + (size_t)(mBase + row) * K + ko + lc;
            asm volatile("cp.async.cg.shared.global [%0], [%1], 16;\n" :: "r"(da), "l"(ga));
            int wr = nBlk + row;
            uint32_t dw = smem_u32(&sW[buf][row * 72 + lc]);
            const bf16* gw = Wp + (size_t)(wr < N ? wr : 0) * K + ko + lc;
            int sz = (wr < N) ? 16 : 0;
            asm volatile("cp.async.cg.shared.global [%0], [%1], 16, %2;\n"
                         :: "r"(dw), "l"(gw), "r"(sz));
        }
    };

#pragma unroll
    for (int s = 0; s < STAGES - 1; s++) {
        if (s < nStages) loadStage(s, s);
        asm volatile("cp.async.commit_group;\n");
    }

    float d0[4] = {0, 0, 0, 0}, d1[4] = {0, 0, 0, 0};
    const int aR = lane & 15;
    const int aC = (lane >> 4) * 8;
    const int bR = warp * 8 + (lane & 7);
    const int bC = ((lane >> 3) & 1) * 8;

    for (int s = 0; s < nStages; s++) {
        if (s + STAGES - 1 < nStages) loadStage(s + STAGES - 1, (s + STAGES - 1) % STAGES);
        asm volatile("cp.async.commit_group;\n");
        asm volatile("cp.async.wait_group %0;\n" :: "n"(STAGES - 1));
        __syncthreads();
        const bf16* pa = sA[s % STAGES];
        const bf16* pw = sW[s % STAGES];
#pragma unroll
        for (int kk = 0; kk < 64; kk += 16) {
            uint32_t a0[4], a1[4], bb[2];
            uint32_t ad0 = smem_u32(&pa[aR * 72 + kk + aC]);
            uint32_t ad1 = smem_u32(&pa[(aR + 16) * 72 + kk + aC]);
            uint32_t adb = smem_u32(&pw[bR * 72 + kk + bC]);
            asm volatile("ldmatrix.sync.aligned.m8n8.x4.shared.b16 {%0,%1,%2,%3}, [%4];\n"
                : "=r"(a0[0]), "=r"(a0[1]), "=r"(a0[2]), "=r"(a0[3]) : "r"(ad0));
            asm volatile("ldmatrix.sync.aligned.m8n8.x4.shared.b16 {%0,%1,%2,%3}, [%4];\n"
                : "=r"(a1[0]), "=r"(a1[1]), "=r"(a1[2]), "=r"(a1[3]) : "r"(ad1));
            asm volatile("ldmatrix.sync.aligned.m8n8.x2.shared.b16 {%0,%1}, [%2];\n"
                : "=r"(bb[0]), "=r"(bb[1]) : "r"(adb));
            asm volatile("mma.sync.aligned.m16n8k16.row.col.f32.bf16.bf16.f32 "
                "{%0,%1,%2,%3}, {%4,%5,%6,%7}, {%8,%9}, {%0,%1,%2,%3};\n"
                : "+f"(d0[0]), "+f"(d0[1]), "+f"(d0[2]), "+f"(d0[3])
                : "r"(a0[0]), "r"(a0[1]), "r"(a0[2]), "r"(a0[3]), "r"(bb[0]), "r"(bb[1]));
            asm volatile("mma.sync.aligned.m16n8k16.row.col.f32.bf16.bf16.f32 "
                "{%0,%1,%2,%3}, {%4,%5,%6,%7}, {%8,%9}, {%0,%1,%2,%3};\n"
                : "+f"(d1[0]), "+f"(d1[1]), "+f"(d1[2]), "+f"(d1[3])
                : "r"(a1[0]), "r"(a1[1]), "r"(a1[2]), "r"(a1[3]), "r"(bb[0]), "r"(bb[1]));
        }
        __syncthreads();
    }

    const int g = lane >> 2, tg = lane & 3;
    const int ncol = nBlk + warp * 8 + tg * 2;
#pragma unroll
    for (int mt = 0; mt < 2; mt++) {
        const float* dd = mt ? d1 : d0;
#pragma unroll
        for (int rr = 0; rr < 2; rr++) {
            int m = mt * 16 + rr * 8 + g;
            int row = mBase + m;
            int prow = pLocal ? (row & 31) : row;
            int orow = remapBT ? ((row & 31) * Tz + (row >> 5)) : row;
#pragma unroll
            for (int cc = 0; cc < 2; cc++) {
                int col = ncol + cc;
                if (col < N) {
                    float v = dd[rr * 2 + cc];
                    if (P)     v += P[(size_t)prow * ldP + col];
                    if (bias1) v += bias1[col];
                    if (bias2) v += bias2[col];
                    Z[(size_t)orow * ldZ + col] = v;
                }
            }
        }
    }
}

// ---------------- fp8 GEMM tile (device fn): one 32x32 N-tile, KTILE=128 e4m3 ----------
__device__ __forceinline__ void gemm_tile8(
    const uint8_t* __restrict__ A, const uint8_t* __restrict__ W,
    float* __restrict__ Z, int kOff, int kLen, int nBlk,
    uint8_t (&sA)[STAGES][32 * 144], uint8_t (&sW)[STAGES][32 * 144])
{
    const int tid  = threadIdx.x;
    const int lane = tid & 31;
    const int warp = tid >> 5;
    const int nStages = kLen >> 7;

    const int lr0 = tid >> 3;
    const int lc  = (tid & 7) * 16;

    auto loadStage = [&](int s, int buf) {
        int ko = (s << 7) + kOff;
#pragma unroll
        for (int half = 0; half < 2; half++) {
            int row = lr0 + half * 16;
            uint32_t da = smem_u32(&sA[buf][row * 144 + lc]);
            const uint8_t* ga = A + (size_t)row * Dz + ko + lc;
            asm volatile("cp.async.cg.shared.global [%0], [%1], 16;\n" :: "r"(da), "l"(ga));
            uint32_t dw = smem_u32(&sW[buf][row * 144 + lc]);
            const uint8_t* gw = W + (size_t)(nBlk + row) * Dz + ko + lc;
            asm volatile("cp.async.cg.shared.global [%0], [%1], 16;\n" :: "r"(dw), "l"(gw));
        }
    };

#pragma unroll
    for (int s = 0; s < STAGES - 1; s++) {
        if (s < nStages) loadStage(s, s);
        asm volatile("cp.async.commit_group;\n");
    }

    float d0[4] = {0, 0, 0, 0}, d1[4] = {0, 0, 0, 0};
    const int aR  = lane & 15;
    const int aCB = (lane >> 4) * 16;
    const int bR  = warp * 8 + (lane & 7);
    const int bCB = ((lane >> 3) & 1) * 16;

    for (int s = 0; s < nStages; s++) {
        if (s + STAGES - 1 < nStages) loadStage(s + STAGES - 1, (s + STAGES - 1) % STAGES);
        asm volatile("cp.async.commit_group;\n");
        asm volatile("cp.async.wait_group %0;\n" :: "n"(STAGES - 1));
        __syncthreads();
        const uint8_t* pa = sA[s % STAGES];
        const uint8_t* pw = sW[s % STAGES];
#pragma unroll
        for (int kk = 0; kk < 128; kk += 32) {
            uint32_t a0[4], a1[4], bb[2];
            uint32_t ad0 = smem_u32(&pa[aR * 144 + kk + aCB]);
            uint32_t ad1 = smem_u32(&pa[(aR + 16) * 144 + kk + aCB]);
            uint32_t adb = smem_u32(&pw[bR * 144 + kk + bCB]);
            asm volatile("ldmatrix.sync.aligned.m8n8.x4.shared.b16 {%0,%1,%2,%3}, [%4];\n"
                : "=r"(a0[0]), "=r"(a0[1]), "=r"(a0[2]), "=r"(a0[3]) : "r"(ad0));
            asm volatile("ldmatrix.sync.aligned.m8n8.x4.shared.b16 {%0,%1,%2,%3}, [%4];\n"
                : "=r"(a1[0]), "=r"(a1[1]), "=r"(a1[2]), "=r"(a1[3]) : "r"(ad1));
            asm volatile("ldmatrix.sync.aligned.m8n8.x2.shared.b16 {%0,%1}, [%2];\n"
                : "=r"(bb[0]), "=r"(bb[1]) : "r"(adb));
            asm volatile("mma.sync.aligned.m16n8k32.row.col.f32.e4m3.e4m3.f32 "
                "{%0,%1,%2,%3}, {%4,%5,%6,%7}, {%8,%9}, {%0,%1,%2,%3};\n"
                : "+f"(d0[0]), "+f"(d0[1]), "+f"(d0[2]), "+f"(d0[3])
                : "r"(a0[0]), "r"(a0[1]), "r"(a0[2]), "r"(a0[3]), "r"(bb[0]), "r"(bb[1]));
            asm volatile("mma.sync.aligned.m16n8k32.row.col.f32.e4m3.e4m3.f32 "
                "{%0,%1,%2,%3}, {%4,%5,%6,%7}, {%8,%9}, {%0,%1,%2,%3};\n"
                : "+f"(d1[0]), "+f"(d1[1]), "+f"(d1[2]), "+f"(d1[3])
                : "r"(a1[0]), "r"(a1[1]), "r"(a1[2]), "r"(a1[3]), "r"(bb[0]), "r"(bb[1]));
        }
        __syncthreads();
    }

    const int g = lane >> 2, tg = lane & 3;
    const int ncol = nBlk + warp * 8 + tg * 2;
#pragma unroll
    for (int mt = 0; mt < 2; mt++) {
        const float* dd = mt ? d1 : d0;
#pragma unroll
        for (int rr = 0; rr < 2; rr++) {
            int m = mt * 16 + rr * 8 + g;
#pragma unroll
            for (int cc = 0; cc < 2; cc++) {
                int col = ncol + cc;
                Z[(size_t)m * Gz + col] = dd[rr * 2 + cc] * UNSCALE;
            }
        }
    }
}

// ---------------- grid barrier (cumulative counter; all nb blocks resident) -------------
__device__ __forceinline__ void gbar(unsigned target) {
    __threadfence();
    __syncthreads();
    if (threadIdx.x == 0) {
        atomicAdd(&g_bar, 1u);
        while (*(volatile unsigned*)&g_bar < target) __nanosleep(32);
        __threadfence();
    }
    __syncthreads();
}

// ---------------- LSTM cell as device fn (reads z via L2 to avoid stale L1) -------------
__device__ __forceinline__ void cell_phase(
    const float* __restrict__ z0, const float* __restrict__ z1,
    const float* __restrict__ z2, const float* __restrict__ pre,
    float* __restrict__ c, uint8_t* __restrict__ h8, bf16* __restrict__ hCopy, int nb)
{
    for (int i = blockIdx.x * 128 + threadIdx.x; i < Bz * Dz; i += nb * 128) {
        int b = i >> 11, d = i & 2047;
        size_t o = (size_t)b * Gz + d;
        float ii = __ldcg(z0 + o)          + __ldcg(z1 + o)          + pre[o];
        float ff = __ldcg(z0 + o + Dz)     + __ldcg(z1 + o + Dz)     + pre[o + Dz];
        float gg = __ldcg(z0 + o + 2 * Dz) + __ldcg(z1 + o + 2 * Dz) + pre[o + 2 * Dz];
        float oo = __ldcg(z0 + o + 3 * Dz) + __ldcg(z1 + o + 3 * Dz) + pre[o + 3 * Dz];
        if (z2) {
            ii += __ldcg(z2 + o);
            ff += __ldcg(z2 + o + Dz);
            gg += __ldcg(z2 + o + 2 * Dz);
            oo += __ldcg(z2 + o + 3 * Dz);
        }
        float si = 1.f / (1.f + expf(-ii));
        float sf = 1.f / (1.f + expf(-ff));
        float so = 1.f / (1.f + expf(-oo));
        float tg = tanhf(gg);
        float cn = sf * c[i] + si * tg;
        c[i] = cn;
        float hv = so * tanhf(cn);
        h8[i] = __nv_cvt_float_to_fp8(hv * HSCALE, __NV_SATFINITE, __NV_E4M3);
        if (hCopy) hCopy[i] = __float2bfloat16(hv);
    }
}

// ---------------- persistent loop kernel: all 20 steps, 4 phases/step --------------------
// nb = gridDim (runtime-sized to full occupancy). Phases:
//   X: 512 jobs {hl@Ah -> slab0, ha@Ahh -> slab1}
//   cellA (slab0+slab1+preA[t] -> h8a)
//   Y: 768 jobs {ha@Lh k-half0 -> slab3, k-half1 -> slab4, hl@Lhh -> slab2}
//   cellL (slab2+slab3+slab4+preL -> h8l, hlAll[t])
__global__ void __launch_bounds__(128)
k_loop(const float* __restrict__ preA, const float* __restrict__ preL,
       float* __restrict__ ca, float* __restrict__ cl,
       uint8_t* __restrict__ h8a, uint8_t* __restrict__ h8l,
       bf16* __restrict__ hlAll, float* __restrict__ zz, int nb)
{
    __shared__ __align__(128) uint8_t sA[STAGES][32 * 144];
    __shared__ __align__(128) uint8_t sW[STAGES][32 * 144];

    const size_t SLAB = (size_t)Bz * Gz;
    unsigned target = 0;

    for (int t = 0; t < Tz; t++) {
        // Phase X: 512 jobs
        for (int j = blockIdx.x; j < 512; j += nb) {
            int m = j >> 8, n = j & 255;
            const uint8_t* A = m ? h8a : h8l;
            const uint8_t* W = m ? g_f8Ahh : g_f8Ah;
            gemm_tile8(A, W, zz + (size_t)m * SLAB, 0, Dz, n * 32, sA, sW);
        }
        target += nb; gbar(target);

        cell_phase(zz, zz + SLAB, nullptr, preA + (size_t)t * SLAB, ca, h8a, nullptr, nb);
        target += nb; gbar(target);

        // Phase Y: 768 jobs
        for (int j = blockIdx.x; j < 768; j += nb) {
            int m = j >> 8, n = j & 255;
            if (m < 2) {
                gemm_tile8(h8a, g_f8Lh, zz + (size_t)(3 + m) * SLAB,
                           m * 1024, 1024, n * 32, sA, sW);
            } else {
                gemm_tile8(h8l, g_f8Lhh, zz + 2 * SLAB, 0, Dz, n * 32, sA, sW);
            }
        }
        target += nb; gbar(target);

        cell_phase(zz + 2 * SLAB, zz + 3 * SLAB, zz + 4 * SLAB, preL,
                   cl, h8l, hlAll + (size_t)t * Bz * Dz, nb);
        target += nb; gbar(target);
    }
}

// ---------------- in-place log_softmax over V per (b,t) row ----------------
__global__ void k_lsm(float* __restrict__ out) {
    __shared__ float red[8];
    int r = blockIdx.x;
    float* p = out + (size_t)r * Vz;
    int tid = threadIdx.x;
    float m = -1e30f;
    for (int i = tid; i < Vz; i += 256) m = fmaxf(m, p[i]);
#pragma unroll
    for (int o = 16; o > 0; o >>= 1) m = fmaxf(m, __shfl_xor_sync(0xffffffffu, m, o));
    if ((tid & 31) == 0) red[tid >> 5] = m;
    __syncthreads();
    if (tid == 0) {
        float mm = red[0];
        for (int j = 1; j < 8; j++) mm = fmaxf(mm, red[j]);
        red[0] = mm;
    }
    __syncthreads();
    m = red[0];
    __syncthreads();
    float s = 0.f;
    for (int i = tid; i < Vz; i += 256) s += expf(p[i] - m);
#pragma unroll
    for (int o = 16; o > 0; o >>= 1) s += __shfl_xor_sync(0xffffffffu, s, o);
    if ((tid & 31) == 0) red[tid >> 5] = s;
    __syncthreads();
    if (tid == 0) {
        float ss = 0.f;
        for (int j = 0; j < 8; j++) ss += red[j];
        red[0] = ss;
    }
    __syncthreads();
    float lse = m + logf(red[0]);
    for (int i = tid; i < Vz; i += 256) p[i] -= lse;
}

// ---------------- host ----------------
extern "C" void kernel_launch(void* const* d_in, const int* in_sizes, int n_in,
                              void* d_out, int out_size) {
    const float* features = (const float*)d_in[0];
    const int*   caption  = (const int*)  d_in[1];
    const float* emb      = (const float*)d_in[2];
    const float* Wih_a    = (const float*)d_in[3];
    const float* Whh_a    = (const float*)d_in[4];
    const float* bih_a    = (const float*)d_in[5];
    const float* bhh_a    = (const float*)d_in[6];
    const float* Wih_l    = (const float*)d_in[7];
    const float* Whh_l    = (const float*)d_in[8];
    const float* bih_l    = (const float*)d_in[9];
    const float* bhh_l    = (const float*)d_in[10];
    const float* Wfc      = (const float*)d_in[17];
    const float* bfc      = (const float*)d_in[18];
    float* out = (float*)d_out;

    uint8_t *f8Ah, *f8Ahh, *f8Lh, *f8Lhh, *h8a, *h8l;
    bf16 *bAv, *bAe, *bLv, *bFC, *embsB, *vbarB, *vhatB, *hlAll;
    float *ca, *cl, *zz, *prevA, *preL, *preA;
    unsigned* barp;
    cudaGetSymbolAddress((void**)&f8Ah,  g_f8Ah);
    cudaGetSymbolAddress((void**)&f8Ahh, g_f8Ahh);
    cudaGetSymbolAddress((void**)&f8Lh,  g_f8Lh);
    cudaGetSymbolAddress((void**)&f8Lhh, g_f8Lhh);
    cudaGetSymbolAddress((void**)&h8a,   g_h8a);
    cudaGetSymbolAddress((void**)&h8l,   g_h8l);
    cudaGetSymbolAddress((void**)&bAv,   g_bAv);
    cudaGetSymbolAddress((void**)&bAe,   g_bAe);
    cudaGetSymbolAddress((void**)&bLv,   g_bLv);
    cudaGetSymbolAddress((void**)&bFC,   g_bFC);
    cudaGetSymbolAddress((void**)&embsB, g_embsB);
    cudaGetSymbolAddress((void**)&vbarB, g_vbarB);
    cudaGetSymbolAddress((void**)&vhatB, g_vhatB);
    cudaGetSymbolAddress((void**)&hlAll, g_hlAll);
    cudaGetSymbolAddress((void**)&ca,    g_caF);
    cudaGetSymbolAddress((void**)&cl,    g_clF);
    cudaGetSymbolAddress((void**)&zz,    g_zF);
    cudaGetSymbolAddress((void**)&prevA, g_prevAF);
    cudaGetSymbolAddress((void**)&preL,  g_preLF);
    cudaGetSymbolAddress((void**)&preA,  g_preAF);
    cudaGetSymbolAddress((void**)&barp,  g_bar);

    // full-occupancy persistent grid (deterministic per capture)
    int nsm = 0, occ = 0;
    cudaDeviceGetAttribute(&nsm, cudaDevAttrMultiProcessorCount, 0);
    cudaOccupancyMaxActiveBlocksPerMultiprocessor(&occ, k_loop, 128, 0);
    if (nsm <= 0) nsm = 148;
    if (occ <= 0) occ = 1;
    int nb = nsm * occ;
    if (nb > 768) nb = 768;   // no benefit past max job count

    // init recurrent state + barrier counter (graph replays need fresh counter)
    cudaMemsetAsync(ca,  0, (size_t)Bz * Dz * sizeof(float));
    cudaMemsetAsync(cl,  0, (size_t)Bz * Dz * sizeof(float));
    cudaMemsetAsync(h8a, 0, (size_t)Bz * Dz);
    cudaMemsetAsync(h8l, 0, (size_t)Bz * Dz);
    cudaMemsetAsync(barp, 0, sizeof(unsigned));

    // one-shot precompute
    k_feat<<<(Bz * Dz + 255) / 256, 256>>>(features);
    k_embs<<<(Bz * Tz * Dz + 255) / 256, 256>>>(emb, caption);

    const int cv4 = Gz * Dz / 4;
    k_conv8<<<cv4 / 256, 256>>>(Wih_a, 3 * Dz, 0,  f8Ah,  cv4);
    k_conv8<<<cv4 / 256, 256>>>(Whh_a, Dz,     0,  f8Ahh, cv4);
    k_conv8<<<cv4 / 256, 256>>>(Wih_l, 2 * Dz, 0,  f8Lh,  cv4);
    k_conv8<<<cv4 / 256, 256>>>(Whh_l, Dz,     0,  f8Lhh, cv4);
    k_conv<<<cv4 / 256, 256>>>(Wih_a, 3 * Dz, Dz,     bAv, cv4);
    k_conv<<<cv4 / 256, 256>>>(Wih_a, 3 * Dz, 2 * Dz, bAe, cv4);
    k_conv<<<cv4 / 256, 256>>>(Wih_l, 2 * Dz, Dz,     bLv, cv4);
    k_conv<<<(Vz * Dz / 4 + 255) / 256, 256>>>(Wfc, Dz, 0, bFC, Vz * Dz / 4);

    dim3 blk(128);
    // prevA[b,:] = v_bar @ bAv^T + bih_a + bhh_a
    k_gemm<<<dim3(Gz / 32, 1), blk>>>(vbarB, bAv, Dz, vbarB, bAv, 0,
                                      nullptr, 0, 0, bih_a, bhh_a, prevA, Gz, Gz, 0);
    // preA[t*32+b,:] = prevA[b,:] + e_{b,t} @ bAe^T
    k_gemm<<<dim3(Gz / 32, Tz), blk>>>(embsB, bAe, Dz, embsB, bAe, 0,
                                       prevA, Gz, 1, nullptr, nullptr, preA, Gz, Gz, 0);
    // preL[b,:] = v_hat @ bLv^T + bih_l + bhh_l
    k_gemm<<<dim3(Gz / 32, 1), blk>>>(vhatB, bLv, Dz, vhatB, bLv, 0,
                                      nullptr, 0, 0, bih_l, bhh_l, preL, Gz, Gz, 0);

    // persistent loop: all 20 steps in one launch, full-occupancy grid
    k_loop<<<nb, blk>>>(preA, preL, ca, cl, h8a, h8l, hlAll, zz, nb);

    // batched logits: rows r=t*32+b of hlAll @ Wfc^T + bfc -> out[b][t][:]
    k_gemm<<<dim3((Vz + 31) / 32, Tz), blk>>>(hlAll, bFC, Dz, hlAll, bFC, 0,
                                              nullptr, 0, 0, bfc, nullptr,
                                              out, Vz, Vz, 1);
    k_lsm<<<Bz * Tz, 256>>>(out);
}